// round 13
// baseline (speedup 1.0000x reference)
#include <cuda_runtime.h>
#include <cuda_bf16.h>
#include <math.h>
#include <stdint.h>

// ---------------------------------------------------------------------------
// Problem constants
// ---------------------------------------------------------------------------
#define BATCH 512
#define MF    48
#define DD    128
#define O1    68
#define O2    32
#define O3    24
#define NPAIR 1176          // 48*49/2 symmetric pairs
#define KDIAG 1224          // + 48 linear (diag) rows
#define KPAD  1280          // padded to 20 tiles of 64
#define NG    144           // GEMM N: 68 xk1 + 4 pad + 68 R' + 4 pad
#define NKT   20            // k-tiles of 64
#define KT    64
#define TILEB (NG*KT*2)     // 18432 bytes per B tile
#define XST   50            // x0 row stride (48 data + 1.0 + 0.0)
#define NTHR  512

// ---------------------------------------------------------------------------
// Device-global scratch (no allocation allowed)
// ---------------------------------------------------------------------------
__device__ unsigned int g_suv[KPAD];
__device__ __align__(16) __nv_bfloat16 g_Bt[NKT * NG * KT];  // packed+swizzled
__device__ float g_F[MF * MF * 64];                          // fc1 lookup

// ---------------------------------------------------------------------------
// Helpers
// ---------------------------------------------------------------------------
__device__ __forceinline__ void pair_decode(int t, int& u, int& v) {
    int k = 0, base = 0;
    while (t >= base + (MF - k)) { base += MF - k; ++k; }
    u = k; v = k + (t - base);
}

__device__ __forceinline__ uint32_t smem_u32(const void* p) {
    uint32_t a;
    asm("{ .reg .u64 t; cvta.to.shared.u64 t, %1; cvt.u32.u64 %0, t; }" : "=r"(a) : "l"(p));
    return a;
}

__device__ __forceinline__ void ldsm_x4(uint32_t& r0, uint32_t& r1,
                                        uint32_t& r2, uint32_t& r3, uint32_t addr) {
    asm volatile("ldmatrix.sync.aligned.m8n8.x4.shared.b16 {%0,%1,%2,%3}, [%4];"
                 : "=r"(r0), "=r"(r1), "=r"(r2), "=r"(r3) : "r"(addr));
}

__device__ __forceinline__ void mma16816(float* c, uint32_t a0, uint32_t a1,
                                         uint32_t a2, uint32_t a3,
                                         uint32_t b0, uint32_t b1) {
    asm volatile(
        "mma.sync.aligned.m16n8k16.row.col.f32.bf16.bf16.f32 "
        "{%0,%1,%2,%3}, {%4,%5,%6,%7}, {%8,%9}, {%0,%1,%2,%3};"
        : "+f"(c[0]), "+f"(c[1]), "+f"(c[2]), "+f"(c[3])
        : "r"(a0), "r"(a1), "r"(a2), "r"(a3), "r"(b0), "r"(b1));
}

__device__ __forceinline__ uint32_t h2mul(__nv_bfloat16 ax, __nv_bfloat16 ay,
                                          __nv_bfloat16 bx, __nv_bfloat16 by) {
    __nv_bfloat162 pa, pb;
    pa.x = ax; pa.y = ay; pb.x = bx; pb.y = by;
    __nv_bfloat162 r = __hmul2(pa, pb);
    return *reinterpret_cast<uint32_t*>(&r);
}

__device__ __forceinline__ void cp16(uint32_t dst, const void* src) {
    asm volatile("cp.async.cg.shared.global [%0], [%1], 16;" :: "r"(dst), "l"(src));
}
#define CP_COMMIT() asm volatile("cp.async.commit_group;" ::: "memory")
#define CP_WAIT0()  asm volatile("cp.async.wait_group 0;" ::: "memory")

// ---------------------------------------------------------------------------
// Single fused prep kernel (851 independent blocks, one wave):
//   [0,6):     suv table
//   [7,199):   F = fc1 lookup table, block = (j, m-quarter), smem-tiled
//   [199,579): wsym-pack + pad zeros (elementwise)
//   [579,851): Tq-pack, block = (a, K-quarter); computes its V3 slice locally
// ---------------------------------------------------------------------------
__global__ void prep_all(const float* __restrict__ w1, const float* __restrict__ w2,
                         const float* __restrict__ w3, const float* __restrict__ out_w,
                         const float* __restrict__ emb, const float* __restrict__ fc1_w) {
    __shared__ float sf[1536 + 8192];      // 38.9 KB, reused per branch
    const int tid = threadIdx.x;
    const int b   = blockIdx.x;

    if (b < 6) {                            // ---- suv ----
        int gid = b * 256 + tid;
        if (gid < KPAD) {
            int u, v;
            if (gid < NPAIR)      { pair_decode(gid, u, v); }
            else if (gid < KDIAG) { u = gid - NPAIR; v = 48; }
            else                  { u = 49; v = 49; }
            g_suv[gid] = (unsigned)u | ((unsigned)v << 16);
        }
        return;
    }

    if (b >= 7 && b < 199) {                // ---- F table ----
        const int fb = b - 7;
        const int j = fb >> 2, q = fb & 3;
        float* se = sf;                      // emb rows q*12..q*12+11
        float* sw = sf + 1536;               // fc1_w slice j
        for (int i = tid; i < 1536; i += 256) se[i] = emb[q * 1536 + i];
        for (int i = tid; i < 8192; i += 256) sw[i] = fc1_w[j * 8192 + i];
        __syncthreads();
        #pragma unroll
        for (int t = 0; t < 3; ++t) {
            int o = t * 256 + tid;
            int m = o >> 6, c = o & 63;
            float s = 0.f;
            #pragma unroll 8
            for (int d = 0; d < DD; ++d) s += se[m * DD + d] * sw[d * 64 + c];
            g_F[((j * MF + q * 12 + m) << 6) + c] = s;
        }
        return;
    }

    if (b >= 199 && b < 579) {              // ---- wsym pack + pads ----
        int idx = (b - 199) * 256 + tid;    // < 76*64*20 = 97280
        int t = idx / (76 * 64);
        int r = idx - t * (76 * 64);
        int nn = r >> 6, kk = r & 63;
        int n = (nn < 72) ? nn : (68 + nn); // [0,72) -> n, 72..75 -> 140..143
        int k = t * 64 + kk;
        float val = 0.f;
        if (n < O1 && k < NPAIR) {
            int u, v; pair_decode(k, u, v);
            val = w1[(u * MF + v) * O1 + n];
            if (u < v) val += w1[(v * MF + u) * O1 + n];
        }
        int chunk = kk >> 3;
        int off = t * TILEB + n * 128 + ((chunk ^ (n & 7)) << 4) + ((kk & 7) << 1);
        *(__nv_bfloat16*)((char*)g_Bt + off) = __float2bfloat16_rn(val);
        return;
    }

    if (b < 579) return;                    // b == 6 spare

    // ---- Tq pack: a = field-out index, q = K-quarter ----
    float* sV  = sf;                        // 1536: V3 computed locally
    float* sw2 = sf + 1536;                 // 1536: w2 slice for row a
    __shared__ float sow[O2];
    const int bb = b - 579;
    const int a = bb >> 2, q = bb & 3;
    const int n = 72 + a;
    for (int i = tid; i < O2 * MF; i += 256) {
        float s = 0.f;
        #pragma unroll
        for (int o = 0; o < O3; ++o) s += w3[i * O3 + o] * out_w[125 + o];
        sV[i] = s;
    }
    for (int i = tid; i < MF * O2; i += 256) sw2[i] = w2[a * (MF * O2) + i];
    if (tid < O2) sow[tid] = out_w[25 + O1 + tid];
    __syncthreads();

    for (int e = tid; e < 320; e += 256) {
        int k = q * 320 + e;
        float val = 0.f;
        if (k < NPAIR) {
            int u, v; pair_decode(k, u, v);
            float s = 0.f;
            const float* r1 = sw2 + u * O2;
            #pragma unroll 8
            for (int k2 = 0; k2 < O2; ++k2) s += r1[k2] * sV[k2 * MF + v];
            if (u < v) {
                const float* r2 = sw2 + v * O2;
                #pragma unroll 8
                for (int k2 = 0; k2 < O2; ++k2) s += r2[k2] * sV[k2 * MF + u];
            }
            val = s;
        } else if (k < KDIAG) {
            int m = k - NPAIR;
            float s = 0.f;
            const float* r1 = sw2 + m * O2;
            #pragma unroll 8
            for (int k2 = 0; k2 < O2; ++k2) s += r1[k2] * sow[k2];
            val = s;
        }
        int t = k >> 6, kk = k & 63;
        int chunk = kk >> 3;
        int off = t * TILEB + n * 128 + ((chunk ^ (n & 7)) << 4) + ((kk & 7) << 1);
        *(__nv_bfloat16*)((char*)g_Bt + off) = __float2bfloat16_rn(val);
    }
}

// ---------------------------------------------------------------------------
// Main fused kernel: one CTA per TWO batch rows, 512 threads / 16 warps.
// (byte-identical numerics to the 158.2us version)
// ---------------------------------------------------------------------------
// dyn smem layout (bytes, from 1024-aligned base)
#define OFF_X0B   0                    // 2 * 128*50 bf16 = 25600
#define OFF_B     25600                // 2 * 18432 = 36864
#define OFF_SUV   62464                // 1280 u32  = 5120
#define OFF_OWP   67584                // 144 f32   = 576
#define OFF_XR    68160                // 2*48 int  = 384
#define OFF_D1    68544                // 2*64 f32
#define OFF_D2    69056                // 2*48 f32
#define OFF_D3    69440                // 2*24 f32
#define OFF_RED   69632                // 16 f32
#define SMEM_DYN  (69696 + 1024)

__global__ __launch_bounds__(NTHR, 1) void cin_main(
    const int*   __restrict__ x,     const float* __restrict__ emb,
    const float* __restrict__ lin_w, const float* __restrict__ lin_b,
    const float* __restrict__ fc1_b,
    const float* __restrict__ bn1_g, const float* __restrict__ bn1_b,
    const float* __restrict__ fc2_w, const float* __restrict__ fc2_b,
    const float* __restrict__ bn2_g, const float* __restrict__ bn2_b,
    const float* __restrict__ fc3_w, const float* __restrict__ fc3_b,
    const float* __restrict__ bn3_g, const float* __restrict__ bn3_b,
    const float* __restrict__ out_w, const float* __restrict__ out_b,
    float* __restrict__ out)
{
    extern __shared__ char smraw[];
    char* sm = (char*)(((uintptr_t)smraw + 1023) & ~(uintptr_t)1023);
    __nv_bfloat16* x0b = (__nv_bfloat16*)(sm + OFF_X0B);  // [2][128][50]
    unsigned int* ssuv = (unsigned int*)(sm + OFF_SUV);
    float*        owp  = (float*)(sm + OFF_OWP);
    int*          xr   = (int*)(sm + OFF_XR);
    float*        d1s  = (float*)(sm + OFF_D1);
    float*        d2s  = (float*)(sm + OFF_D2);
    float*        d3s  = (float*)(sm + OFF_D3);
    float*        red  = (float*)(sm + OFF_RED);

    const int tid  = threadIdx.x;
    const int lane = tid & 31;
    const int warp = tid >> 5;       // 0..15
    const uint32_t s32 = smem_u32(sm);

    if (tid < 2 * MF) xr[tid] = x[blockIdx.x * (2 * MF) + tid];
    for (int i = tid; i < NG; i += NTHR) owp[i] = (i < O1) ? out_w[25 + i] : 0.f;
    for (int i = tid; i < KPAD; i += NTHR) ssuv[i] = g_suv[i];
    __syncthreads();

    // gather both samples' x0 transposed (bf16): x0b[smp*6400 + d*50 + j]
    for (int i = tid; i < 2 * DD * XST; i += NTHR) {
        int smp = i / (DD * XST);
        int rr  = i - smp * (DD * XST);
        int d = rr / XST, j = rr - d * XST;
        float v;
        if (j < MF)       v = emb[(xr[smp * MF + j] << 7) + d];
        else if (j == 48) v = 1.0f;
        else              v = 0.0f;
        x0b[i] = __float2bfloat16_rn(v);
    }

    // prologue: cp.async B tile 0 into buf0
    for (int i = tid; i < TILEB / 16; i += NTHR)
        cp16(s32 + OFF_B + i * 16, (const char*)g_Bt + i * 16);
    CP_COMMIT();
    CP_WAIT0();
    __syncthreads();

    // per-warp fragment geometry: m-tile = warp>>1, sample = warp&1
    const int wsmp  = warp & 1;
    const int rbase = wsmp * 6400 + (((warp >> 1) * 16) + (lane >> 2)) * XST;
    const __nv_bfloat16* rA0 = x0b + rbase;
    const __nv_bfloat16* rA1 = rA0 + 8 * XST;
    const int kq    = (lane & 3) << 1;
    const int matq  = lane >> 3;
    const int nloc  = ((matq >= 2) ? 8 : 0) + (lane & 7);
    const int cksel = matq & 1;

    float acc[18][4];
    #pragma unroll
    for (int i = 0; i < 18; ++i)
        #pragma unroll
        for (int r = 0; r < 4; ++r) acc[i][r] = 0.f;

    for (int t = 0; t < NKT; ++t) {
        const int buf = t & 1;
        if (t < NKT - 1) {
            const char* src = (const char*)g_Bt + (t + 1) * TILEB;
            uint32_t dst = s32 + OFF_B + (buf ^ 1) * TILEB;
            for (int i = tid; i < TILEB / 16; i += NTHR)
                cp16(dst + i * 16, src + i * 16);
            CP_COMMIT();
        }
        const uint32_t Bb = s32 + OFF_B + buf * TILEB;
        const int k0 = t * 64;

        #pragma unroll
        for (int s = 0; s < 4; ++s) {
            const int ks = s << 4;
            const int kg = k0 + ks + kq;
            unsigned p0 = ssuv[kg],     p1 = ssuv[kg + 1];
            unsigned p8 = ssuv[kg + 8], p9 = ssuv[kg + 9];
            const int u0 = p0 & 0xFFFF, w0i = p0 >> 16;
            const int u1 = p1 & 0xFFFF, w1i = p1 >> 16;
            const int u8 = p8 & 0xFFFF, w8i = p8 >> 16;
            const int u9 = p9 & 0xFFFF, w9i = p9 >> 16;
            uint32_t a0 = h2mul(rA0[u0], rA0[u1], rA0[w0i], rA0[w1i]);
            uint32_t a1 = h2mul(rA1[u0], rA1[u1], rA1[w0i], rA1[w1i]);
            uint32_t a2 = h2mul(rA0[u8], rA0[u9], rA0[w8i], rA0[w9i]);
            uint32_t a3 = h2mul(rA1[u8], rA1[u9], rA1[w8i], rA1[w9i]);

            const int chunk = (ks >> 3) + cksel;
            #pragma unroll
            for (int q = 0; q < 9; ++q) {
                const int n = q * 16 + nloc;
                uint32_t baddr = Bb + n * 128 + (uint32_t)((chunk ^ (n & 7)) << 4);
                uint32_t b0, b1, b2, b3;
                ldsm_x4(b0, b1, b2, b3, baddr);
                mma16816(acc[2 * q],     a0, a1, a2, a3, b0, b1);
                mma16816(acc[2 * q + 1], a0, a1, a2, a3, b2, b3);
            }
        }
        if (t < NKT - 1) CP_WAIT0();
        __syncthreads();
    }

    // ---- epilogue straight from accumulator registers ----
    float part = 0.f;
    #pragma unroll
    for (int nt = 0; nt < 9; ++nt) {
        const float w0 = owp[nt * 8 + kq];
        const float w1v = owp[nt * 8 + kq + 1];
        #pragma unroll
        for (int r = 0; r < 4; ++r) {
            float wv = (r & 1) ? w1v : w0;
            float xa = acc[nt][r];
            part += xa * acc[nt + 9][r] + wv * xa;
        }
    }
    #pragma unroll
    for (int off = 16; off; off >>= 1)
        part += __shfl_xor_sync(0xffffffffu, part, off);
    if (lane == 0) red[warp] = part;

    // ---- deep MLP (fp32 exact): half-block per sample ----
    const int smp = tid >> 8;        // 0 or 1
    const int t1  = tid & 255;
    const int* xrs = xr + smp * MF;
    const float invs = rsqrtf(1.0f + 1e-3f);
    __syncthreads();
    if (t1 < 64) {
        float a = fc1_b[t1];
        #pragma unroll
        for (int j = 0; j < MF; ++j) a += g_F[((j * MF + xrs[j]) << 6) + t1];
        a = fmaxf(a, 0.f);
        d1s[smp * 64 + t1] = bn1_g[t1] * a * invs + bn1_b[t1];
    }
    __syncthreads();
    if (t1 < 48) {
        float a = fc2_b[t1];
        const float* d1 = d1s + smp * 64;
        #pragma unroll 8
        for (int i = 0; i < 64; ++i) a += d1[i] * fc2_w[i * 48 + t1];
        a = tanhf(a);
        d2s[smp * 48 + t1] = bn2_g[t1] * a * invs + bn2_b[t1];
    }
    __syncthreads();
    if (t1 < 24) {
        float a = fc3_b[t1];
        const float* d2 = d2s + smp * 48;
        #pragma unroll 8
        for (int i = 0; i < 48; ++i) a += d2[i] * fc3_w[i * 24 + t1];
        a = tanhf(a);
        d3s[smp * 24 + t1] = bn3_g[t1] * a * invs + bn3_b[t1];
    }
    __syncthreads();

    if (t1 == 0) {
        float lg = out_b[0];
        #pragma unroll
        for (int w = 0; w < 8; ++w) lg += red[2 * w + smp];
        const float* d3 = d3s + smp * 24;
        #pragma unroll
        for (int c = 0; c < 24; ++c) lg += d3[c] * out_w[c];
        float sl = lin_b[0];
        #pragma unroll
        for (int j = 0; j < MF; ++j) sl += (float)xrs[j] * lin_w[j];
        lg += tanhf(sl) * out_w[24];
        out[blockIdx.x * 2 + smp] = 1.0f / (1.0f + expf(-lg));
    }
}

// ---------------------------------------------------------------------------
// Launch
// ---------------------------------------------------------------------------
extern "C" void kernel_launch(void* const* d_in, const int* in_sizes, int n_in,
                              void* d_out, int out_size)
{
    const int*   x     = (const int*)  d_in[0];
    const float* emb   = (const float*)d_in[1];
    const float* w1    = (const float*)d_in[2];
    const float* w2    = (const float*)d_in[3];
    const float* w3    = (const float*)d_in[4];
    const float* lin_w = (const float*)d_in[5];
    const float* lin_b = (const float*)d_in[6];
    const float* fc1_w = (const float*)d_in[7];
    const float* fc1_b = (const float*)d_in[8];
    const float* bn1_g = (const float*)d_in[9];
    const float* bn1_b = (const float*)d_in[10];
    const float* bn2_g = (const float*)d_in[13];
    const float* fc2_w = (const float*)d_in[11];
    const float* fc2_b = (const float*)d_in[12];
    const float* bn2_b = (const float*)d_in[14];
    const float* fc3_w = (const float*)d_in[15];
    const float* fc3_b = (const float*)d_in[16];
    const float* bn3_g = (const float*)d_in[17];
    const float* bn3_b = (const float*)d_in[18];
    const float* out_w = (const float*)d_in[19];
    const float* out_b = (const float*)d_in[20];
    float* out = (float*)d_out;

    prep_all<<<851, 256>>>(w1, w2, w3, out_w, emb, fc1_w);

    cudaFuncSetAttribute(cin_main, cudaFuncAttributeMaxDynamicSharedMemorySize, SMEM_DYN);
    cin_main<<<BATCH / 2, NTHR, SMEM_DYN>>>(
        x, emb, lin_w, lin_b, fc1_b, bn1_g, bn1_b,
        fc2_w, fc2_b, bn2_g, bn2_b, fc3_w, fc3_b, bn3_g, bn3_b,
        out_w, out_b, out);
}

// round 14
// speedup vs baseline: 1.1424x; 1.1424x over previous
#include <cuda_runtime.h>
#include <cuda_bf16.h>
#include <math.h>
#include <stdint.h>

// ---------------------------------------------------------------------------
// Problem constants
// ---------------------------------------------------------------------------
#define BATCH 512
#define MF    48
#define DD    128
#define O1    68
#define O2    32
#define O3    24
#define KPAD  1344          // 21 tiles of 64 (run-padded K)
#define KUSED 1296          // sum of padded run lengths
#define NG    144           // interleaved: n=2a -> xk1[a], n=2a+1 -> R'[a]; 136..143 pad
#define NKT   21            // k-tiles of 64
#define KT    64
#define TILEB (NG*KT*2)     // 18432 bytes per B tile
#define XST   50            // x0 row stride in bf16 (48 fields + 1.0 + 0.0)
#define NPR   (KPAD/2)      // 672 pair entries
#define NTHR  512

// ---------------------------------------------------------------------------
// Device-global scratch (no allocation allowed)
// ---------------------------------------------------------------------------
__device__ unsigned int g_pr[NPR];                           // per-pair (uoff | voff<<16)
__device__ __align__(16) __nv_bfloat16 g_Bt[NKT * NG * KT];  // packed+swizzled B
__device__ float g_F[MF * MF * 64];                          // fc1 lookup

// ---------------------------------------------------------------------------
// Helpers
// ---------------------------------------------------------------------------
// K layout: runs u=0..47; run u holds v = (u&~1) .. 49 (v=48 -> x0*1.0 linear,
// v=49 -> zero pad). All runs even-length; k >= KUSED is tail (zero).
// Returns false for tail.
__device__ __forceinline__ bool decode_slot(int k, int& u, int& v) {
    if (k >= KUSED) return false;
    int S = 0;
    #pragma unroll 1
    for (u = 0; u < 48; ++u) {
        int len = 50 - (u & ~1);
        if (k < S + len) { v = (u & ~1) + (k - S); return true; }
        S += len;
    }
    return false;
}

__device__ __forceinline__ uint32_t smem_u32(const void* p) {
    uint32_t a;
    asm("{ .reg .u64 t; cvta.to.shared.u64 t, %1; cvt.u32.u64 %0, t; }" : "=r"(a) : "l"(p));
    return a;
}

__device__ __forceinline__ void ldsm_x4(uint32_t& r0, uint32_t& r1,
                                        uint32_t& r2, uint32_t& r3, uint32_t addr) {
    asm volatile("ldmatrix.sync.aligned.m8n8.x4.shared.b16 {%0,%1,%2,%3}, [%4];"
                 : "=r"(r0), "=r"(r1), "=r"(r2), "=r"(r3) : "r"(addr));
}

__device__ __forceinline__ void mma16816(float* c, uint32_t a0, uint32_t a1,
                                         uint32_t a2, uint32_t a3,
                                         uint32_t b0, uint32_t b1) {
    asm volatile(
        "mma.sync.aligned.m16n8k16.row.col.f32.bf16.bf16.f32 "
        "{%0,%1,%2,%3}, {%4,%5,%6,%7}, {%8,%9}, {%0,%1,%2,%3};"
        : "+f"(c[0]), "+f"(c[1]), "+f"(c[2]), "+f"(c[3])
        : "r"(a0), "r"(a1), "r"(a2), "r"(a3), "r"(b0), "r"(b1));
}

// splat(su) * (vlo, vhi)
__device__ __forceinline__ uint32_t h2sv(__nv_bfloat16 su, uint32_t vv) {
    __nv_bfloat162 s2; s2.x = su; s2.y = su;
    __nv_bfloat162 v2 = *reinterpret_cast<__nv_bfloat162*>(&vv);
    __nv_bfloat162 r = __hmul2(s2, v2);
    return *reinterpret_cast<uint32_t*>(&r);
}

__device__ __forceinline__ void cp16(uint32_t dst, const void* src) {
    asm volatile("cp.async.cg.shared.global [%0], [%1], 16;" :: "r"(dst), "l"(src));
}
#define CP_COMMIT() asm volatile("cp.async.commit_group;" ::: "memory")
#define CP_WAIT0()  asm volatile("cp.async.wait_group 0;" ::: "memory")

// ---------------------------------------------------------------------------
// Fused prep kernel (337 blocks):
//   [0]        : g_pr pair table
//   [1,193)    : F = fc1 lookup table, block = (j, m-quarter)
//   [193,337)  : B-pack, one block per column n
// ---------------------------------------------------------------------------
__global__ void prep_all(const float* __restrict__ w1, const float* __restrict__ w2,
                         const float* __restrict__ w3, const float* __restrict__ out_w,
                         const float* __restrict__ emb, const float* __restrict__ fc1_w) {
    __shared__ float sf[1536 + 8192];     // reused per branch
    const int tid = threadIdx.x;
    const int b   = blockIdx.x;

    if (b == 0) {                          // ---- pair table ----
        for (int p = tid; p < NPR; p += 256) {
            int u, v;
            if (!decode_slot(2 * p, u, v)) { u = 49; v = 48; }
            g_pr[p] = (unsigned)(u * 2) | ((unsigned)(v * 2) << 16);
        }
        return;
    }

    if (b < 193) {                         // ---- F table ----
        const int fb = b - 1;
        const int j = fb >> 2, q = fb & 3;
        float* se = sf;                    // emb rows q*12..q*12+11
        float* sw = sf + 1536;             // fc1_w slice j
        for (int i = tid; i < 1536; i += 256) se[i] = emb[q * 1536 + i];
        for (int i = tid; i < 8192; i += 256) sw[i] = fc1_w[j * 8192 + i];
        __syncthreads();
        #pragma unroll
        for (int t = 0; t < 3; ++t) {
            int o = t * 256 + tid;
            int m = o >> 6, c = o & 63;
            float s = 0.f;
            #pragma unroll 8
            for (int d = 0; d < DD; ++d) s += se[m * DD + d] * sw[d * 64 + c];
            g_F[((j * MF + q * 12 + m) << 6) + c] = s;
        }
        return;
    }

    // ---- B pack: one block per column n ----
    const int n = b - 193;                 // 0..143
    const int a = n >> 1, side = n & 1;
    __shared__ float sow[O2];
    if (side == 0) {
        // stage w1 column a: w1col[j] = w1[j*O1 + a], j < 2304
        float* w1col = sf;
        if (a < O1)
            for (int i = tid; i < MF * MF; i += 256) w1col[i] = w1[i * O1 + a];
        __syncthreads();
        for (int k = tid; k < KPAD; k += 256) {
            int u, v; float val = 0.f;
            if (a < O1 && decode_slot(k, u, v) && v < 48) {
                bool sameblk = ((u >> 1) == (v >> 1));
                val = w1col[u * MF + v];
                if (!sameblk) val += w1col[v * MF + u];
            }
            int t = k >> 6, kk = k & 63, chunk = kk >> 3;
            int off = t * TILEB + n * 128 + ((chunk ^ (n & 7)) << 4) + ((kk & 7) << 1);
            *(__nv_bfloat16*)((char*)g_Bt + off) = __float2bfloat16_rn(val);
        }
        return;
    }
    // side == 1: R' column — stage V3 + w2 row a + ow2
    float* sV  = sf;                       // [O2][MF]
    float* sw2 = sf + 1536;                // [MF][O2] = w2[a]
    for (int i = tid; i < O2 * MF; i += 256) {
        float s = 0.f;
        #pragma unroll
        for (int o = 0; o < O3; ++o) s += w3[i * O3 + o] * out_w[125 + o];
        sV[i] = s;
    }
    if (a < O1)
        for (int i = tid; i < MF * O2; i += 256) sw2[i] = w2[a * (MF * O2) + i];
    if (tid < O2) sow[tid] = out_w[25 + O1 + tid];
    __syncthreads();
    for (int k = tid; k < KPAD; k += 256) {
        int u, v; float val = 0.f;
        if (a < O1 && decode_slot(k, u, v)) {
            if (v < 48) {
                bool sameblk = ((u >> 1) == (v >> 1));
                float s = 0.f;
                #pragma unroll 8
                for (int k2 = 0; k2 < O2; ++k2) s += sw2[u * O2 + k2] * sV[k2 * MF + v];
                if (!sameblk) {
                    #pragma unroll 8
                    for (int k2 = 0; k2 < O2; ++k2) s += sw2[v * O2 + k2] * sV[k2 * MF + u];
                }
                val = s;
            } else if (v == 48) {
                float s = 0.f;
                #pragma unroll 8
                for (int k2 = 0; k2 < O2; ++k2) s += sw2[u * O2 + k2] * sow[k2];
                val = s;
            }
        }
        int t = k >> 6, kk = k & 63, chunk = kk >> 3;
        int off = t * TILEB + n * 128 + ((chunk ^ (n & 7)) << 4) + ((kk & 7) << 1);
        *(__nv_bfloat16*)((char*)g_Bt + off) = __float2bfloat16_rn(val);
    }
}

// ---------------------------------------------------------------------------
// Main fused kernel: one CTA per TWO batch rows, 512 threads / 16 warps.
// warp = (sample = w&1, n-half = (w>>1)&1, m-pair = w>>2): each warp covers
// 2 m-tiles x half of N -> per-warp B LDSM halves; paired A-gen (scalar+4B).
// ---------------------------------------------------------------------------
// dyn smem layout (bytes, from 1024-aligned base)
#define OFF_X0B   0                    // 2 * 128*50 bf16 = 25600
#define OFF_B     25600                // 2 * 18432 = 36864 -> 62464
#define OFF_PR    62464                // 672 u32 = 2688 -> 65152
#define OFF_OWP   65152                // 72 f32 = 288 -> 65440
#define OFF_XR    65440                // 2*48 int -> 65824
#define OFF_D1    65824                // 2*64 f32 -> 66336
#define OFF_D2    66336                // 2*48 f32 -> 66720
#define OFF_D3    66720                // 2*24 f32 -> 66912
#define OFF_RED   66912                // 16 f32 -> 66976
#define SMEM_DYN  (66976 + 1024)

__global__ __launch_bounds__(NTHR, 1) void cin_main(
    const int*   __restrict__ x,     const float* __restrict__ emb,
    const float* __restrict__ lin_w, const float* __restrict__ lin_b,
    const float* __restrict__ fc1_b,
    const float* __restrict__ bn1_g, const float* __restrict__ bn1_b,
    const float* __restrict__ fc2_w, const float* __restrict__ fc2_b,
    const float* __restrict__ bn2_g, const float* __restrict__ bn2_b,
    const float* __restrict__ fc3_w, const float* __restrict__ fc3_b,
    const float* __restrict__ bn3_g, const float* __restrict__ bn3_b,
    const float* __restrict__ out_w, const float* __restrict__ out_b,
    float* __restrict__ out)
{
    extern __shared__ char smraw[];
    char* sm = (char*)(((uintptr_t)smraw + 1023) & ~(uintptr_t)1023);
    __nv_bfloat16* x0b = (__nv_bfloat16*)(sm + OFF_X0B);   // [2][128][50]
    unsigned int*  spr = (unsigned int*)(sm + OFF_PR);
    float*         owp = (float*)(sm + OFF_OWP);           // [72]
    int*           xr  = (int*)(sm + OFF_XR);
    float*         d1s = (float*)(sm + OFF_D1);
    float*         d2s = (float*)(sm + OFF_D2);
    float*         d3s = (float*)(sm + OFF_D3);
    float*         red = (float*)(sm + OFF_RED);

    const int tid  = threadIdx.x;
    const int lane = tid & 31;
    const int warp = tid >> 5;       // 0..15
    const uint32_t s32 = smem_u32(sm);

    if (tid < 2 * MF) xr[tid] = x[blockIdx.x * (2 * MF) + tid];
    for (int i = tid; i < 72; i += NTHR) owp[i] = (i < O1) ? out_w[25 + i] : 0.f;
    for (int i = tid; i < NPR; i += NTHR) spr[i] = g_pr[i];
    __syncthreads();

    // gather both samples' x0 transposed (bf16): x0b[smp*6400 + d*50 + j]
    for (int i = tid; i < 2 * DD * XST; i += NTHR) {
        int smp = i / (DD * XST);
        int rr  = i - smp * (DD * XST);
        int d = rr / XST, j = rr - d * XST;
        float v;
        if (j < MF)       v = emb[(xr[smp * MF + j] << 7) + d];
        else if (j == 48) v = 1.0f;
        else              v = 0.0f;
        x0b[i] = __float2bfloat16_rn(v);
    }

    // prologue: cp.async B tile 0
    for (int i = tid; i < TILEB / 16; i += NTHR)
        cp16(s32 + OFF_B + i * 16, (const char*)g_Bt + i * 16);
    CP_COMMIT();
    CP_WAIT0();
    __syncthreads();

    // warp geometry
    const int wsmp = warp & 1;
    const int nh   = (warp >> 1) & 1;
    const int mp   = warp >> 2;                  // 0..3, rows 32*mp..32*mp+31
    const int nq    = 5 - nh;                    // 5 or 4 q-subtiles
    const int qbase = nh * 5;
    const int kqh  = lane & 3;                   // pair id within kstep
    const int kq   = kqh << 1;
    const int matq = lane >> 3;
    const int nloc = ((matq >= 2) ? 8 : 0) + (lane & 7);
    const int cksel = matq & 1;

    // 4 row byte-pointers: rows mp*32 + (lane>>2) + {0,8,16,24}
    const char* xbase = (const char*)x0b + wsmp * (DD * XST * 2)
                        + (mp * 32 + (lane >> 2)) * (XST * 2);
    const char* xp0 = xbase;
    const char* xp1 = xbase + 8  * (XST * 2);
    const char* xp2 = xbase + 16 * (XST * 2);
    const char* xp3 = xbase + 24 * (XST * 2);

    float acc[80];                               // [mt:2][qi:5][j:2][r:4]
    #pragma unroll
    for (int i = 0; i < 80; ++i) acc[i] = 0.f;

    for (int t = 0; t < NKT; ++t) {
        const int buf = t & 1;
        if (t < NKT - 1) {
            const char* src = (const char*)g_Bt + (t + 1) * TILEB;
            uint32_t dst = s32 + OFF_B + (buf ^ 1) * TILEB;
            for (int i = tid; i < TILEB / 16; i += NTHR)
                cp16(dst + i * 16, src + i * 16);
            CP_COMMIT();
        }
        const uint32_t Bb = s32 + OFF_B + buf * TILEB;

        #pragma unroll
        for (int s = 0; s < 4; ++s) {
            const int p0 = t * 32 + s * 8 + kqh;
            const unsigned pr0 = spr[p0], pr1 = spr[p0 + 4];
            const unsigned uo0 = pr0 & 0xFFFFu, vo0 = pr0 >> 16;
            const unsigned uo1 = pr1 & 0xFFFFu, vo1 = pr1 >> 16;

            // A fragments: pairs (k even: x0[u]*x0[v0], k odd: x0[u]*x0[v0+1])
            uint32_t a0 = h2sv(*(const __nv_bfloat16*)(xp0 + uo0), *(const uint32_t*)(xp0 + vo0));
            uint32_t a1 = h2sv(*(const __nv_bfloat16*)(xp1 + uo0), *(const uint32_t*)(xp1 + vo0));
            uint32_t a2 = h2sv(*(const __nv_bfloat16*)(xp0 + uo1), *(const uint32_t*)(xp0 + vo1));
            uint32_t a3 = h2sv(*(const __nv_bfloat16*)(xp1 + uo1), *(const uint32_t*)(xp1 + vo1));
            uint32_t c0 = h2sv(*(const __nv_bfloat16*)(xp2 + uo0), *(const uint32_t*)(xp2 + vo0));
            uint32_t c1 = h2sv(*(const __nv_bfloat16*)(xp3 + uo0), *(const uint32_t*)(xp3 + vo0));
            uint32_t c2 = h2sv(*(const __nv_bfloat16*)(xp2 + uo1), *(const uint32_t*)(xp2 + vo1));
            uint32_t c3 = h2sv(*(const __nv_bfloat16*)(xp3 + uo1), *(const uint32_t*)(xp3 + vo1));

            const int chunk = (s << 1) + cksel;
            #pragma unroll
            for (int qi = 0; qi < 5; ++qi) {
                if (qi < nq) {
                    const int n = (qbase + qi) * 16 + nloc;
                    uint32_t baddr = Bb + n * 128 + (uint32_t)((chunk ^ (n & 7)) << 4);
                    uint32_t b0, b1, b2, b3;
                    ldsm_x4(b0, b1, b2, b3, baddr);
                    mma16816(acc + qi * 8,          a0, a1, a2, a3, b0, b1);
                    mma16816(acc + qi * 8 + 4,      a0, a1, a2, a3, b2, b3);
                    mma16816(acc + 40 + qi * 8,     c0, c1, c2, c3, b0, b1);
                    mma16816(acc + 40 + qi * 8 + 4, c0, c1, c2, c3, b2, b3);
                }
            }
        }
        if (t < NKT - 1) CP_WAIT0();
        __syncthreads();
    }

    // ---- epilogue: pairs are adjacent columns (2a, 2a+1) within each quad ----
    float part = 0.f;
    #pragma unroll
    for (int mt = 0; mt < 2; ++mt) {
        #pragma unroll
        for (int qi = 0; qi < 5; ++qi) {
            if (qi < nq) {
                #pragma unroll
                for (int j = 0; j < 2; ++j) {
                    const int col0 = (qbase + qi) * 16 + j * 8 + kq;   // even
                    const float ow = owp[col0 >> 1];
                    const float* c = acc + mt * 40 + qi * 8 + j * 4;
                    part += c[0] * c[1] + ow * c[0] + c[2] * c[3] + ow * c[2];
                }
            }
        }
    }
    #pragma unroll
    for (int off = 16; off; off >>= 1)
        part += __shfl_xor_sync(0xffffffffu, part, off);
    if (lane == 0) red[warp] = part;

    // ---- deep MLP (fp32 exact): half-block per sample ----
    const int smp = tid >> 8;        // 0 or 1
    const int t1  = tid & 255;
    const int* xrs = xr + smp * MF;
    const float invs = rsqrtf(1.0f + 1e-3f);
    __syncthreads();
    if (t1 < 64) {
        float a = fc1_b[t1];
        #pragma unroll
        for (int j = 0; j < MF; ++j) a += g_F[((j * MF + xrs[j]) << 6) + t1];
        a = fmaxf(a, 0.f);
        d1s[smp * 64 + t1] = bn1_g[t1] * a * invs + bn1_b[t1];
    }
    __syncthreads();
    if (t1 < 48) {
        float a = fc2_b[t1];
        const float* d1 = d1s + smp * 64;
        #pragma unroll 8
        for (int i = 0; i < 64; ++i) a += d1[i] * fc2_w[i * 48 + t1];
        a = tanhf(a);
        d2s[smp * 48 + t1] = bn2_g[t1] * a * invs + bn2_b[t1];
    }
    __syncthreads();
    if (t1 < 24) {
        float a = fc3_b[t1];
        const float* d2 = d2s + smp * 48;
        #pragma unroll 8
        for (int i = 0; i < 48; ++i) a += d2[i] * fc3_w[i * 24 + t1];
        a = tanhf(a);
        d3s[smp * 24 + t1] = bn3_g[t1] * a * invs + bn3_b[t1];
    }
    __syncthreads();

    if (t1 == 0) {
        float lg = out_b[0];
        #pragma unroll
        for (int w = 0; w < 8; ++w) lg += red[2 * w + smp];
        const float* d3 = d3s + smp * 24;
        #pragma unroll
        for (int c = 0; c < 24; ++c) lg += d3[c] * out_w[c];
        float sl = lin_b[0];
        #pragma unroll
        for (int j = 0; j < MF; ++j) sl += (float)xrs[j] * lin_w[j];
        lg += tanhf(sl) * out_w[24];
        out[blockIdx.x * 2 + smp] = 1.0f / (1.0f + expf(-lg));
    }
}

// ---------------------------------------------------------------------------
// Launch
// ---------------------------------------------------------------------------
extern "C" void kernel_launch(void* const* d_in, const int* in_sizes, int n_in,
                              void* d_out, int out_size)
{
    const int*   x     = (const int*)  d_in[0];
    const float* emb   = (const float*)d_in[1];
    const float* w1    = (const float*)d_in[2];
    const float* w2    = (const float*)d_in[3];
    const float* w3    = (const float*)d_in[4];
    const float* lin_w = (const float*)d_in[5];
    const float* lin_b = (const float*)d_in[6];
    const float* fc1_w = (const float*)d_in[7];
    const float* fc1_b = (const float*)d_in[8];
    const float* bn1_g = (const float*)d_in[9];
    const float* bn1_b = (const float*)d_in[10];
    const float* fc2_w = (const float*)d_in[11];
    const float* fc2_b = (const float*)d_in[12];
    const float* bn2_g = (const float*)d_in[13];
    const float* bn2_b = (const float*)d_in[14];
    const float* fc3_w = (const float*)d_in[15];
    const float* fc3_b = (const float*)d_in[16];
    const float* bn3_g = (const float*)d_in[17];
    const float* bn3_b = (const float*)d_in[18];
    const float* out_w = (const float*)d_in[19];
    const float* out_b = (const float*)d_in[20];
    float* out = (float*)d_out;

    prep_all<<<337, 256>>>(w1, w2, w3, out_w, emb, fc1_w);

    cudaFuncSetAttribute(cin_main, cudaFuncAttributeMaxDynamicSharedMemorySize, SMEM_DYN);
    cin_main<<<BATCH / 2, NTHR, SMEM_DYN>>>(
        x, emb, lin_w, lin_b, fc1_b, bn1_g, bn1_b,
        fc2_w, fc2_b, bn2_g, bn2_b, fc3_w, fc3_b, bn3_g, bn3_b,
        out_w, out_b, out);
}